// round 1
// baseline (speedup 1.0000x reference)
#include <cuda_runtime.h>
#include <cuda_bf16.h>
#include <cstdint>

#define Bb 4
#define Ss 1024
#define Dd 1024
#define Hh 16
#define DHh 64
#define SCALE 0.125f

// ---------------- scratch (device globals; no allocation allowed) ----------------
__device__ float g_Q[Bb * Hh * Ss * DHh];   // [b][h][s][d]
__device__ float g_K[Bb * Hh * Ss * DHh];
__device__ float g_V[Bb * Hh * Ss * DHh];
__device__ float g_CQ[Bb * Ss * DHh];       // [b][s][d]
__device__ float g_CK[Bb * Ss * DHh];
__device__ float g_lam[Bb * Hh * Ss];       // lambda_context
__device__ float g_qsig[Bb * Ss * Ss];      // sigmoid quasi scores (head-invariant)

__device__ __forceinline__ float sigmoidf_(float x) { return 1.0f / (1.0f + __expf(-x)); }

// ---------------- kernel 1: QKV projection GEMM (M=4096,N=1024,K=1024) -----------
// 128x128 block, 8x8 per thread, BK=16. Scatter output to [B,H,S,DH].
__global__ __launch_bounds__(256, 2) void proj_gemm(
    const float* __restrict__ A, const float* __restrict__ W,
    const float* __restrict__ bias, int which)
{
    __shared__ float As[16][132];
    __shared__ float Bs[16][132];
    float* out = (which == 0) ? g_Q : (which == 1) ? g_K : g_V;

    const int bm = blockIdx.y;            // 0..31
    const int bn = blockIdx.x;            // 0..7
    const int tid = threadIdx.x;
    const int tx = tid & 15, ty = tid >> 4;

    float acc[8][8];
#pragma unroll
    for (int i = 0; i < 8; i++)
#pragma unroll
        for (int j = 0; j < 8; j++) acc[i][j] = 0.0f;

    for (int k0 = 0; k0 < 1024; k0 += 16) {
        // A tile: 128 rows x 16 cols, store transposed As[k][m]
#pragma unroll
        for (int i = 0; i < 2; i++) {
            int idx = tid + i * 256;          // 0..511
            int row = idx >> 2;               // 0..127
            int c4  = idx & 3;                // 0..3
            float4 v = *(const float4*)&A[(size_t)(bm * 128 + row) * 1024 + k0 + c4 * 4];
            As[c4 * 4 + 0][row] = v.x;
            As[c4 * 4 + 1][row] = v.y;
            As[c4 * 4 + 2][row] = v.z;
            As[c4 * 4 + 3][row] = v.w;
        }
        // B tile: 16 rows x 128 cols
#pragma unroll
        for (int i = 0; i < 2; i++) {
            int idx = tid + i * 256;
            int row = idx >> 5;               // 0..15
            int c4  = idx & 31;               // 0..31
            float4 v = *(const float4*)&W[(size_t)(k0 + row) * 1024 + bn * 128 + c4 * 4];
            *(float4*)&Bs[row][c4 * 4] = v;
        }
        __syncthreads();
#pragma unroll
        for (int kk = 0; kk < 16; kk++) {
            float4 a0 = *(float4*)&As[kk][ty * 8];
            float4 a1 = *(float4*)&As[kk][ty * 8 + 4];
            float4 b0 = *(float4*)&Bs[kk][tx * 8];
            float4 b1 = *(float4*)&Bs[kk][tx * 8 + 4];
            float a[8] = {a0.x, a0.y, a0.z, a0.w, a1.x, a1.y, a1.z, a1.w};
            float bvv[8] = {b0.x, b0.y, b0.z, b0.w, b1.x, b1.y, b1.z, b1.w};
#pragma unroll
            for (int i = 0; i < 8; i++)
#pragma unroll
                for (int j = 0; j < 8; j++) acc[i][j] += a[i] * bvv[j];
        }
        __syncthreads();
    }

    // epilogue: scatter to [B,H,S,DH]
#pragma unroll
    for (int i = 0; i < 8; i++) {
        int m = bm * 128 + ty * 8 + i;        // b*S + s
        int b = m >> 10, s = m & 1023;
#pragma unroll
        for (int j = 0; j < 8; j++) {
            int n = bn * 128 + tx * 8 + j;    // h*DH + d
            int h = n >> 6, d = n & 63;
            out[(((size_t)(b * Hh + h) * Ss + s) * DHh) + d] = acc[i][j] + bias[n];
        }
    }
}

// ---------------- kernel 2: CQ/CK projections (N=64 each) ------------------------
__global__ void cqck_kernel(
    const float* __restrict__ C,
    const float* __restrict__ Wcq, const float* __restrict__ bcq,
    const float* __restrict__ Wck, const float* __restrict__ bck)
{
    __shared__ float xs[1024];
    const int row = blockIdx.x;       // b*S + s
    const int t = threadIdx.x;        // 0..63
    for (int i = t; i < 1024; i += 64) xs[i] = C[(size_t)row * 1024 + i];
    __syncthreads();
    float aq = 0.f, ak = 0.f;
#pragma unroll 8
    for (int i = 0; i < 1024; i++) {
        float x = xs[i];
        aq += x * Wcq[i * 64 + t];
        ak += x * Wck[i * 64 + t];
    }
    g_CQ[(size_t)row * 64 + t] = aq + bcq[t];
    g_CK[(size_t)row * 64 + t] = ak + bck[t];
}

// ---------------- kernel 3: lambda_context [B,H,S] -------------------------------
__global__ void lam_kernel(
    const float* __restrict__ wlqc, const float* __restrict__ wlqq,
    const float* __restrict__ wlkc, const float* __restrict__ wlkk)
{
    const int idx = blockIdx.x * 8 + threadIdx.y;  // 0..65535 = (b*H+h)*S+s
    const int lane = threadIdx.x;
    const int b = idx >> 14;
    const int s = idx & 1023;
    const float* q  = &g_Q[(size_t)idx * 64];
    const float* k  = &g_K[(size_t)idx * 64];
    const float* cq = &g_CQ[((size_t)b * Ss + s) * 64];
    const float* ck = &g_CK[((size_t)b * Ss + s) * 64];
    float sq = cq[lane] * wlqc[lane] + cq[lane + 32] * wlqc[lane + 32]
             + q[lane]  * wlqq[lane] + q[lane + 32]  * wlqq[lane + 32];
    float sk = ck[lane] * wlkc[lane] + ck[lane + 32] * wlkc[lane + 32]
             + k[lane]  * wlkk[lane] + k[lane + 32]  * wlkk[lane + 32];
#pragma unroll
    for (int o = 16; o > 0; o >>= 1) {
        sq += __shfl_xor_sync(0xffffffffu, sq, o);
        sk += __shfl_xor_sync(0xffffffffu, sk, o);
    }
    if (lane == 0) g_lam[idx] = 1.0f - sigmoidf_(sq) - sigmoidf_(sk);
}

// ---------------- kernel 4: head-invariant quasi sigmoid [B,S,S] ------------------
__global__ __launch_bounds__(256) void qsig_kernel(const float* __restrict__ mask)
{
    __shared__ float Qs[64 * 68];     // [d][qrow]
    __shared__ float Ks[64 * 68];     // [d][krow]
    const int bi = blockIdx.z, qt = blockIdx.y, kt = blockIdx.x;
    const int tid = threadIdx.x;
    const int tx = tid & 15, ty = tid >> 4;

#pragma unroll
    for (int i = 0; i < 4; i++) {
        int idx = tid + i * 256;           // 0..1023
        int m = idx >> 4, c4 = idx & 15;
        float4 vq = *(const float4*)&g_CQ[((size_t)(bi * Ss + qt * 64 + m)) * 64 + c4 * 4];
        float4 vk = *(const float4*)&g_CK[((size_t)(bi * Ss + kt * 64 + m)) * 64 + c4 * 4];
        Qs[(c4 * 4 + 0) * 68 + m] = vq.x; Qs[(c4 * 4 + 1) * 68 + m] = vq.y;
        Qs[(c4 * 4 + 2) * 68 + m] = vq.z; Qs[(c4 * 4 + 3) * 68 + m] = vq.w;
        Ks[(c4 * 4 + 0) * 68 + m] = vk.x; Ks[(c4 * 4 + 1) * 68 + m] = vk.y;
        Ks[(c4 * 4 + 2) * 68 + m] = vk.z; Ks[(c4 * 4 + 3) * 68 + m] = vk.w;
    }
    __syncthreads();

    float acc[4][4];
#pragma unroll
    for (int i = 0; i < 4; i++)
#pragma unroll
        for (int j = 0; j < 4; j++) acc[i][j] = 0.0f;

#pragma unroll 4
    for (int d = 0; d < 64; d++) {
        float4 a4 = *(float4*)&Qs[d * 68 + ty * 4];
        float4 b4 = *(float4*)&Ks[d * 68 + tx * 4];
        float a[4] = {a4.x, a4.y, a4.z, a4.w};
        float bv[4] = {b4.x, b4.y, b4.z, b4.w};
#pragma unroll
        for (int i = 0; i < 4; i++)
#pragma unroll
            for (int j = 0; j < 4; j++) acc[i][j] += a[i] * bv[j];
    }
#pragma unroll
    for (int i = 0; i < 4; i++) {
        int qrow = qt * 64 + ty * 4 + i;
#pragma unroll
        for (int j = 0; j < 4; j++) {
            int kcol = kt * 64 + tx * 4 + j;
            float v = sigmoidf_(acc[i][j] * SCALE + mask[bi * Ss + kcol]);
            g_qsig[((size_t)(bi * Ss + qrow)) * Ss + kcol] = v;
        }
    }
}

// ---------------- kernel 5: fused attention ---------------------------------------
// grid (qb=32, bh=64); 256 threads; dynamic smem:
//   Sc[32][1024] scores/new-probs, Qs[64][34] Q^T tile, Ks[64*260] K^T / V tile
#define ATTN_SMEM ((32 * 1024 + 64 * 34 + 64 * 260) * 4)

__global__ __launch_bounds__(256, 1) void attn_kernel(
    const float* __restrict__ mask, float* __restrict__ out)
{
    extern __shared__ float sm[];
    float* Sc = sm;                        // 32768 floats
    float* Qs = Sc + 32 * 1024;            // 64*34
    float* Ks = Qs + 64 * 34;              // 64*260 (reused as V tile 64*68)

    const int qb = blockIdx.x;             // 0..31
    const int bh = blockIdx.y;             // b*H + h
    const int bi = bh >> 4;
    const int hi = bh & 15;
    const int tid = threadIdx.x;

    const float* Qg = &g_Q[((size_t)bh * Ss + qb * 32) * 64];
    const float* Kg = &g_K[(size_t)bh * Ss * 64];
    const float* Vg = &g_V[(size_t)bh * Ss * 64];

    const size_t OFF_NEW   = (size_t)Bb * Ss * Dd;                 // 4194304
    const size_t OFF_PROBS = OFF_NEW + (size_t)Bb * Hh * Ss * Ss;  // 71303168
    const size_t OFF_QUASI = OFF_PROBS + (size_t)Bb * Hh * Ss * Ss;

    // load Q tile [32][64] transposed -> Qs[d*34 + m]
#pragma unroll
    for (int i = 0; i < 2; i++) {
        int idx = tid + i * 256;       // 0..511
        int m = idx >> 4, c4 = idx & 15;
        float4 v = *(const float4*)&Qg[(size_t)m * 64 + c4 * 4];
        Qs[(c4 * 4 + 0) * 34 + m] = v.x;
        Qs[(c4 * 4 + 1) * 34 + m] = v.y;
        Qs[(c4 * 4 + 2) * 34 + m] = v.z;
        Qs[(c4 * 4 + 3) * 34 + m] = v.w;
    }

    // ---------- Phase A: scores Sc[32][1024] = Q @ K^T * scale + mask ----------
    {
        const int tyA = tid >> 5;      // 0..7 -> rows {ty, ty+8, ty+16, ty+24}
        const int txA = tid & 31;      // cols txA*8 .. +7
        for (int nt = 0; nt < 4; nt++) {
            // load K rows nt*256..+255, transposed -> Ks[d*260 + n]
#pragma unroll
            for (int i = 0; i < 16; i++) {
                int idx = tid + i * 256;          // 0..4095
                int n = idx >> 4, c4 = idx & 15;
                float4 v = *(const float4*)&Kg[((size_t)(nt * 256 + n)) * 64 + c4 * 4];
                Ks[(c4 * 4 + 0) * 260 + n] = v.x;
                Ks[(c4 * 4 + 1) * 260 + n] = v.y;
                Ks[(c4 * 4 + 2) * 260 + n] = v.z;
                Ks[(c4 * 4 + 3) * 260 + n] = v.w;
            }
            __syncthreads();

            float acc[4][8];
#pragma unroll
            for (int i = 0; i < 4; i++)
#pragma unroll
                for (int j = 0; j < 8; j++) acc[i][j] = 0.0f;

#pragma unroll 4
            for (int kk = 0; kk < 64; kk++) {
                float a[4];
#pragma unroll
                for (int i = 0; i < 4; i++) a[i] = Qs[kk * 34 + tyA + 8 * i];
                float4 b0 = *(float4*)&Ks[kk * 260 + txA * 8];
                float4 b1 = *(float4*)&Ks[kk * 260 + txA * 8 + 4];
                float bv[8] = {b0.x, b0.y, b0.z, b0.w, b1.x, b1.y, b1.z, b1.w};
#pragma unroll
                for (int i = 0; i < 4; i++)
#pragma unroll
                    for (int j = 0; j < 8; j++) acc[i][j] += a[i] * bv[j];
            }
            // write with scale + mask
#pragma unroll
            for (int i = 0; i < 4; i++) {
                int row = tyA + 8 * i;
                int col = nt * 256 + txA * 8;
                float4 m0, m1;
                m0.x = acc[i][0] * SCALE + mask[bi * Ss + col + 0];
                m0.y = acc[i][1] * SCALE + mask[bi * Ss + col + 1];
                m0.z = acc[i][2] * SCALE + mask[bi * Ss + col + 2];
                m0.w = acc[i][3] * SCALE + mask[bi * Ss + col + 3];
                m1.x = acc[i][4] * SCALE + mask[bi * Ss + col + 4];
                m1.y = acc[i][5] * SCALE + mask[bi * Ss + col + 5];
                m1.z = acc[i][6] * SCALE + mask[bi * Ss + col + 6];
                m1.w = acc[i][7] * SCALE + mask[bi * Ss + col + 7];
                *(float4*)&Sc[row * 1024 + col] = m0;
                *(float4*)&Sc[row * 1024 + col + 4] = m1;
            }
            __syncthreads();
        }
    }

    // ---------- Phase B: softmax + quasi gating + global prob writes ----------
    {
        const int warp = tid >> 5;
        const int lane = tid & 31;
        for (int r = warp * 4; r < warp * 4 + 4; r++) {
            float mx = -1e30f;
            for (int c = lane; c < 1024; c += 32) mx = fmaxf(mx, Sc[r * 1024 + c]);
#pragma unroll
            for (int o = 16; o > 0; o >>= 1) mx = fmaxf(mx, __shfl_xor_sync(0xffffffffu, mx, o));
            float sum = 0.0f;
            for (int c = lane; c < 1024; c += 32) {
                float e = __expf(Sc[r * 1024 + c] - mx);
                Sc[r * 1024 + c] = e;
                sum += e;
            }
#pragma unroll
            for (int o = 16; o > 0; o >>= 1) sum += __shfl_xor_sync(0xffffffffu, sum, o);
            float inv = 1.0f / sum;

            const int qrow = qb * 32 + r;
            const float lam = g_lam[(size_t)bh * Ss + qrow];
            const float* qs_row = &g_qsig[((size_t)(bi * Ss + qrow)) * Ss];
            const size_t rowbase = ((size_t)bh * Ss + qrow) * Ss;
            float* probs_row = out + OFF_PROBS + rowbase;
            float* quasi_row = out + OFF_QUASI + rowbase;
            float* new_row   = out + OFF_NEW + rowbase;

            for (int c4 = lane; c4 < 256; c4 += 32) {
                float4 p = *(float4*)&Sc[r * 1024 + c4 * 4];
                p.x *= inv; p.y *= inv; p.z *= inv; p.w *= inv;
                float4 qs = *(const float4*)&qs_row[c4 * 4];
                float4 qp = {lam * qs.x, lam * qs.y, lam * qs.z, lam * qs.w};
                float4 np = {p.x + qp.x, p.y + qp.y, p.z + qp.z, p.w + qp.w};
                *(float4*)&probs_row[c4 * 4] = p;
                *(float4*)&quasi_row[c4 * 4] = qp;
                *(float4*)&new_row[c4 * 4] = np;
                *(float4*)&Sc[r * 1024 + c4 * 4] = np;
            }
        }
    }
    __syncthreads();

    // ---------- Phase C: ctx[32][64] = newP[32][1024] @ V[1024][64] ----------
    {
        const int tyC = tid >> 4;      // 0..15 -> rows {ty, ty+16}
        const int txC = tid & 15;      // cols txC*4 .. +3
        float acc[2][4];
#pragma unroll
        for (int i = 0; i < 2; i++)
#pragma unroll
            for (int j = 0; j < 4; j++) acc[i][j] = 0.0f;

        for (int kt = 0; kt < 16; kt++) {
            // load V tile [64][64] (row = k position) into Ks with stride 68
#pragma unroll
            for (int i = 0; i < 4; i++) {
                int idx = tid + i * 256;          // 0..1023
                int kk = idx >> 4, c4 = idx & 15;
                float4 v = *(const float4*)&Vg[((size_t)(kt * 64 + kk)) * 64 + c4 * 4];
                *(float4*)&Ks[kk * 68 + c4 * 4] = v;
            }
            __syncthreads();
#pragma unroll 4
            for (int kk = 0; kk < 64; kk++) {
                float a0 = Sc[tyC * 1024 + kt * 64 + kk];
                float a1 = Sc[(tyC + 16) * 1024 + kt * 64 + kk];
                float4 b4 = *(float4*)&Ks[kk * 68 + txC * 4];
                float bv[4] = {b4.x, b4.y, b4.z, b4.w};
#pragma unroll
                for (int j = 0; j < 4; j++) {
                    acc[0][j] += a0 * bv[j];
                    acc[1][j] += a1 * bv[j];
                }
            }
            __syncthreads();
        }
#pragma unroll
        for (int i = 0; i < 2; i++) {
            int qrow = qb * 32 + tyC + 16 * i;
#pragma unroll
            for (int j = 0; j < 4; j++) {
                out[((size_t)(bi * Ss + qrow)) * Dd + hi * 64 + txC * 4 + j] = acc[i][j];
            }
        }
    }
}

// ---------------- launch ----------------------------------------------------------
extern "C" void kernel_launch(void* const* d_in, const int* in_sizes, int n_in,
                              void* d_out, int out_size)
{
    (void)in_sizes; (void)n_in; (void)out_size;
    const float* hidden = (const float*)d_in[0];
    const float* mask   = (const float*)d_in[1];
    const float* ctxemb = (const float*)d_in[2];
    const float* Wq = (const float*)d_in[3];  const float* bq = (const float*)d_in[4];
    const float* Wk = (const float*)d_in[5];  const float* bk = (const float*)d_in[6];
    const float* Wv = (const float*)d_in[7];  const float* bv = (const float*)d_in[8];
    const float* Wcq = (const float*)d_in[9]; const float* bcq = (const float*)d_in[10];
    const float* Wck = (const float*)d_in[11];const float* bck = (const float*)d_in[12];
    const float* wlqc = (const float*)d_in[13];
    const float* wlqq = (const float*)d_in[14];
    const float* wlkc = (const float*)d_in[15];
    const float* wlkk = (const float*)d_in[16];
    float* out = (float*)d_out;

    proj_gemm<<<dim3(8, 32), 256>>>(hidden, Wq, bq, 0);
    proj_gemm<<<dim3(8, 32), 256>>>(hidden, Wk, bk, 1);
    proj_gemm<<<dim3(8, 32), 256>>>(hidden, Wv, bv, 2);
    cqck_kernel<<<Bb * Ss, 64>>>(ctxemb, Wcq, bcq, Wck, bck);
    lam_kernel<<<(Bb * Hh * Ss) / 8, dim3(32, 8)>>>(wlqc, wlqq, wlkc, wlkk);
    qsig_kernel<<<dim3(16, 16, Bb), 256>>>(mask);

    cudaFuncSetAttribute(attn_kernel, cudaFuncAttributeMaxDynamicSharedMemorySize, ATTN_SMEM);
    attn_kernel<<<dim3(32, 64), 256, ATTN_SMEM>>>(mask, out);
}

// round 3
// speedup vs baseline: 1.3314x; 1.3314x over previous
#include <cuda_runtime.h>
#include <cuda_bf16.h>
#include <cstdint>

#define Bb 4
#define Ss 1024
#define Dd 1024
#define Hh 16
#define DHh 64
#define SCALE 0.125f

// ---------------- scratch (device globals; no allocation allowed) ----------------
__device__ float g_Q[Bb * Hh * Ss * DHh];   // [b][h][s][d]
__device__ float g_K[Bb * Hh * Ss * DHh];
__device__ float g_V[Bb * Hh * Ss * DHh];
__device__ float g_CQ[Bb * Ss * DHh];       // [b][s][d]
__device__ float g_CK[Bb * Ss * DHh];
__device__ float g_qsig[Bb * Ss * Ss];      // sigmoid quasi scores (head-invariant)

__device__ __forceinline__ float sigmoidf_(float x) { return 1.0f / (1.0f + __expf(-x)); }

__device__ __forceinline__ uint32_t f2tf(float x) {
    uint32_t r; asm("cvt.rna.tf32.f32 %0, %1;" : "=r"(r) : "f"(x)); return r;
}

__device__ __forceinline__ void mma_tf32(float* d, const uint32_t* a, const uint32_t* b) {
    asm volatile(
        "mma.sync.aligned.m16n8k8.row.col.f32.tf32.tf32.f32 "
        "{%0,%1,%2,%3}, {%4,%5,%6,%7}, {%8,%9}, {%0,%1,%2,%3};"
        : "+f"(d[0]), "+f"(d[1]), "+f"(d[2]), "+f"(d[3])
        : "r"(a[0]), "r"(a[1]), "r"(a[2]), "r"(a[3]), "r"(b[0]), "r"(b[1]));
}

// ---------------- tf32 MMA projection GEMM: [4096,1024] @ [1024,1024] -------------
// BM=128 BN=128 BK=32, 256 threads = 8 warps (2M x 4N), warp tile 64x32.
__global__ __launch_bounds__(256, 2) void proj_mma(
    const float* __restrict__ A, const float* __restrict__ W,
    const float* __restrict__ bias, int which)
{
    __shared__ uint32_t As[128][36];   // [m][k], tf32 bits
    __shared__ uint32_t Bs[32][132];   // [k][n], tf32 bits
    float* out = (which == 0) ? g_Q : (which == 1) ? g_K : g_V;

    const int bm = blockIdx.y, bn = blockIdx.x;
    const int tid = threadIdx.x;
    const int warpId = tid >> 5, lane = tid & 31;
    const int warpM = warpId & 1, warpN = warpId >> 1;
    const int gr = lane >> 2;      // 0..7
    const int gc = lane & 3;       // 0..3

    float acc[4][4][4];
#pragma unroll
    for (int i = 0; i < 4; i++)
#pragma unroll
        for (int j = 0; j < 4; j++)
#pragma unroll
            for (int t = 0; t < 4; t++) acc[i][j][t] = 0.0f;

    for (int k0 = 0; k0 < 1024; k0 += 32) {
        // A tile 128x32 -> As[m][k]
#pragma unroll
        for (int i = 0; i < 4; i++) {
            int idx = tid + i * 256;          // 0..1023
            int r = idx >> 3, c4 = idx & 7;
            float4 v = *(const float4*)&A[(size_t)(bm * 128 + r) * 1024 + k0 + c4 * 4];
            uint4 t = {f2tf(v.x), f2tf(v.y), f2tf(v.z), f2tf(v.w)};
            *(uint4*)&As[r][c4 * 4] = t;
        }
        // B tile 32x128 -> Bs[k][n]
#pragma unroll
        for (int i = 0; i < 4; i++) {
            int idx = tid + i * 256;
            int row = idx >> 5, c4 = idx & 31;
            float4 v = *(const float4*)&W[(size_t)(k0 + row) * 1024 + bn * 128 + c4 * 4];
            uint4 t = {f2tf(v.x), f2tf(v.y), f2tf(v.z), f2tf(v.w)};
            *(uint4*)&Bs[row][c4 * 4] = t;
        }
        __syncthreads();

#pragma unroll
        for (int ks = 0; ks < 4; ks++) {
            const int kb = ks * 8;
            uint32_t af[4][4];
#pragma unroll
            for (int mt = 0; mt < 4; mt++) {
                int m = warpM * 64 + mt * 16;
                af[mt][0] = As[m + gr][kb + gc];
                af[mt][1] = As[m + gr + 8][kb + gc];
                af[mt][2] = As[m + gr][kb + gc + 4];
                af[mt][3] = As[m + gr + 8][kb + gc + 4];
            }
            uint32_t bf[4][2];
#pragma unroll
            for (int nt = 0; nt < 4; nt++) {
                int n = warpN * 32 + nt * 8 + gr;
                bf[nt][0] = Bs[kb + gc][n];
                bf[nt][1] = Bs[kb + gc + 4][n];
            }
#pragma unroll
            for (int mt = 0; mt < 4; mt++)
#pragma unroll
                for (int nt = 0; nt < 4; nt++)
                    mma_tf32(acc[mt][nt], af[mt], bf[nt]);
        }
        __syncthreads();
    }

    // epilogue: scatter to [B,H,S,DH] with bias
#pragma unroll
    for (int mt = 0; mt < 4; mt++) {
        int m0 = bm * 128 + warpM * 64 + mt * 16 + gr;
#pragma unroll
        for (int half = 0; half < 2; half++) {
            int m = m0 + half * 8;
            int b = m >> 10, s = m & 1023;
#pragma unroll
            for (int nt = 0; nt < 4; nt++) {
                int n = bn * 128 + warpN * 32 + nt * 8 + gc * 2;
                int h = n >> 6, d = n & 63;
                float2 v;
                v.x = acc[mt][nt][half * 2 + 0] + bias[n];
                v.y = acc[mt][nt][half * 2 + 1] + bias[n + 1];
                *(float2*)&out[(((size_t)(b * Hh + h) * Ss + s)) * 64 + d] = v;
            }
        }
    }
}

// ---------------- tf32 MMA CQ|CK GEMM: [4096,1024] @ [1024, 64|64] ----------------
// B tile is 32 rows x 128 cols: cols 0..63 = Wcq, cols 64..127 = Wck.
__global__ __launch_bounds__(256, 2) void cqck_mma(
    const float* __restrict__ A,
    const float* __restrict__ Wcq, const float* __restrict__ bcq,
    const float* __restrict__ Wck, const float* __restrict__ bck)
{
    __shared__ uint32_t As[128][36];
    __shared__ uint32_t Bs[32][132];

    const int bm = blockIdx.x;
    const int tid = threadIdx.x;
    const int warpId = tid >> 5, lane = tid & 31;
    const int warpM = warpId & 1, warpN = warpId >> 1;
    const int gr = lane >> 2, gc = lane & 3;

    float acc[4][4][4];
#pragma unroll
    for (int i = 0; i < 4; i++)
#pragma unroll
        for (int j = 0; j < 4; j++)
#pragma unroll
            for (int t = 0; t < 4; t++) acc[i][j][t] = 0.0f;

    for (int k0 = 0; k0 < 1024; k0 += 32) {
#pragma unroll
        for (int i = 0; i < 4; i++) {
            int idx = tid + i * 256;
            int r = idx >> 3, c4 = idx & 7;
            float4 v = *(const float4*)&A[(size_t)(bm * 128 + r) * 1024 + k0 + c4 * 4];
            uint4 t = {f2tf(v.x), f2tf(v.y), f2tf(v.z), f2tf(v.w)};
            *(uint4*)&As[r][c4 * 4] = t;
        }
        // B tile 32 rows x 128 cols (FIXED decode: row=idx>>5, c4=idx&31)
#pragma unroll
        for (int i = 0; i < 4; i++) {
            int idx = tid + i * 256;          // 0..1023
            int row = idx >> 5;               // 0..31
            int c4  = idx & 31;               // 0..31
            int col = c4 * 4;                 // 0..124
            const float* src = (col < 64)
                ? &Wcq[(size_t)(k0 + row) * 64 + col]
                : &Wck[(size_t)(k0 + row) * 64 + (col - 64)];
            float4 v = *(const float4*)src;
            uint4 t = {f2tf(v.x), f2tf(v.y), f2tf(v.z), f2tf(v.w)};
            *(uint4*)&Bs[row][col] = t;
        }
        __syncthreads();

#pragma unroll
        for (int ks = 0; ks < 4; ks++) {
            const int kb = ks * 8;
            uint32_t af[4][4];
#pragma unroll
            for (int mt = 0; mt < 4; mt++) {
                int m = warpM * 64 + mt * 16;
                af[mt][0] = As[m + gr][kb + gc];
                af[mt][1] = As[m + gr + 8][kb + gc];
                af[mt][2] = As[m + gr][kb + gc + 4];
                af[mt][3] = As[m + gr + 8][kb + gc + 4];
            }
            uint32_t bf[4][2];
#pragma unroll
            for (int nt = 0; nt < 4; nt++) {
                int n = warpN * 32 + nt * 8 + gr;
                bf[nt][0] = Bs[kb + gc][n];
                bf[nt][1] = Bs[kb + gc + 4][n];
            }
#pragma unroll
            for (int mt = 0; mt < 4; mt++)
#pragma unroll
                for (int nt = 0; nt < 4; nt++)
                    mma_tf32(acc[mt][nt], af[mt], bf[nt]);
        }
        __syncthreads();
    }

#pragma unroll
    for (int mt = 0; mt < 4; mt++) {
        int m0 = bm * 128 + warpM * 64 + mt * 16 + gr;
#pragma unroll
        for (int half = 0; half < 2; half++) {
            int m = m0 + half * 8;     // = b*S + s
#pragma unroll
            for (int nt = 0; nt < 4; nt++) {
                int n = warpN * 32 + nt * 8 + gc * 2;
                float2 v;
                if (n < 64) {
                    v.x = acc[mt][nt][half * 2 + 0] + bcq[n];
                    v.y = acc[mt][nt][half * 2 + 1] + bcq[n + 1];
                    *(float2*)&g_CQ[(size_t)m * 64 + n] = v;
                } else {
                    v.x = acc[mt][nt][half * 2 + 0] + bck[n - 64];
                    v.y = acc[mt][nt][half * 2 + 1] + bck[n - 63];
                    *(float2*)&g_CK[(size_t)m * 64 + (n - 64)] = v;
                }
            }
        }
    }
}

// ---------------- head-invariant quasi sigmoid [B,S,S] ---------------------------
__global__ __launch_bounds__(256) void qsig_kernel(const float* __restrict__ mask)
{
    __shared__ float Qs[64 * 68];     // [d][qrow]
    __shared__ float Ks[64 * 68];     // [d][krow]
    const int bi = blockIdx.z, qt = blockIdx.y, kt = blockIdx.x;
    const int tid = threadIdx.x;
    const int tx = tid & 15, ty = tid >> 4;

#pragma unroll
    for (int i = 0; i < 4; i++) {
        int idx = tid + i * 256;           // 0..1023
        int m = idx >> 4, c4 = idx & 15;
        float4 vq = *(const float4*)&g_CQ[((size_t)(bi * Ss + qt * 64 + m)) * 64 + c4 * 4];
        float4 vk = *(const float4*)&g_CK[((size_t)(bi * Ss + kt * 64 + m)) * 64 + c4 * 4];
        Qs[(c4 * 4 + 0) * 68 + m] = vq.x; Qs[(c4 * 4 + 1) * 68 + m] = vq.y;
        Qs[(c4 * 4 + 2) * 68 + m] = vq.z; Qs[(c4 * 4 + 3) * 68 + m] = vq.w;
        Ks[(c4 * 4 + 0) * 68 + m] = vk.x; Ks[(c4 * 4 + 1) * 68 + m] = vk.y;
        Ks[(c4 * 4 + 2) * 68 + m] = vk.z; Ks[(c4 * 4 + 3) * 68 + m] = vk.w;
    }
    __syncthreads();

    float acc[4][4];
#pragma unroll
    for (int i = 0; i < 4; i++)
#pragma unroll
        for (int j = 0; j < 4; j++) acc[i][j] = 0.0f;

#pragma unroll 4
    for (int d = 0; d < 64; d++) {
        float4 a4 = *(float4*)&Qs[d * 68 + ty * 4];
        float4 b4 = *(float4*)&Ks[d * 68 + tx * 4];
        float a[4] = {a4.x, a4.y, a4.z, a4.w};
        float bv[4] = {b4.x, b4.y, b4.z, b4.w};
#pragma unroll
        for (int i = 0; i < 4; i++)
#pragma unroll
            for (int j = 0; j < 4; j++) acc[i][j] += a[i] * bv[j];
    }
#pragma unroll
    for (int i = 0; i < 4; i++) {
        int qrow = qt * 64 + ty * 4 + i;
#pragma unroll
        for (int j = 0; j < 4; j++) {
            int kcol = kt * 64 + tx * 4 + j;
            float v = sigmoidf_(acc[i][j] * SCALE + mask[bi * Ss + kcol]);
            g_qsig[((size_t)(bi * Ss + qrow)) * Ss + kcol] = v;
        }
    }
}

// ---------------- fused attention (lambda computed inline) ------------------------
#define ATTN_SMEM ((32 * 1024 + 64 * 34 + 64 * 260 + 32) * 4)

__global__ __launch_bounds__(256, 1) void attn_kernel(
    const float* __restrict__ mask, float* __restrict__ out,
    const float* __restrict__ wlqc, const float* __restrict__ wlqq,
    const float* __restrict__ wlkc, const float* __restrict__ wlkk)
{
    extern __shared__ float sm[];
    float* Sc = sm;                        // 32768 floats
    float* Qs = Sc + 32 * 1024;            // 64*34
    float* Ks = Qs + 64 * 34;              // 64*260 (reused as V tile 64*68)
    float* lam_s = Ks + 64 * 260;          // 32 floats

    const int qb = blockIdx.x;             // 0..31
    const int bh = blockIdx.y;             // b*H + h
    const int bi = bh >> 4;
    const int hi = bh & 15;
    const int tid = threadIdx.x;

    const float* Qg = &g_Q[((size_t)bh * Ss + qb * 32) * 64];
    const float* Kg = &g_K[(size_t)bh * Ss * 64];
    const float* Vg = &g_V[(size_t)bh * Ss * 64];

    const size_t OFF_NEW   = (size_t)Bb * Ss * Dd;
    const size_t OFF_PROBS = OFF_NEW + (size_t)Bb * Hh * Ss * Ss;
    const size_t OFF_QUASI = OFF_PROBS + (size_t)Bb * Hh * Ss * Ss;

    // load Q tile [32][64] transposed -> Qs[d*34 + m]
#pragma unroll
    for (int i = 0; i < 2; i++) {
        int idx = tid + i * 256;       // 0..511
        int m = idx >> 4, c4 = idx & 15;
        float4 v = *(const float4*)&Qg[(size_t)m * 64 + c4 * 4];
        Qs[(c4 * 4 + 0) * 34 + m] = v.x;
        Qs[(c4 * 4 + 1) * 34 + m] = v.y;
        Qs[(c4 * 4 + 2) * 34 + m] = v.z;
        Qs[(c4 * 4 + 3) * 34 + m] = v.w;
    }

    // inline lambda_context for this block's 32 query rows
    {
        int r = tid >> 3;          // 0..31
        int j = tid & 7;           // 0..7
        int qrow = qb * 32 + r;
        const float* cq = &g_CQ[((size_t)(bi * Ss + qrow)) * 64];
        const float* ck = &g_CK[((size_t)(bi * Ss + qrow)) * 64];
        const float* qp = &Qg[(size_t)r * 64];
        const float* kp = &Kg[((size_t)(qb * 32 + r)) * 64];
        float sq = 0.f, sk = 0.f;
#pragma unroll
        for (int d0 = 0; d0 < 8; d0++) {
            int d = j * 8 + d0;
            sq += cq[d] * wlqc[d] + qp[d] * wlqq[d];
            sk += ck[d] * wlkc[d] + kp[d] * wlkk[d];
        }
#pragma unroll
        for (int o = 4; o > 0; o >>= 1) {
            sq += __shfl_xor_sync(0xffffffffu, sq, o);
            sk += __shfl_xor_sync(0xffffffffu, sk, o);
        }
        if (j == 0) lam_s[r] = 1.0f - sigmoidf_(sq) - sigmoidf_(sk);
    }

    // ---------- Phase A: scores Sc[32][1024] = Q @ K^T * scale + mask ----------
    {
        const int tyA = tid >> 5;
        const int txA = tid & 31;
        for (int nt = 0; nt < 4; nt++) {
#pragma unroll
            for (int i = 0; i < 16; i++) {
                int idx = tid + i * 256;
                int n = idx >> 4, c4 = idx & 15;
                float4 v = *(const float4*)&Kg[((size_t)(nt * 256 + n)) * 64 + c4 * 4];
                Ks[(c4 * 4 + 0) * 260 + n] = v.x;
                Ks[(c4 * 4 + 1) * 260 + n] = v.y;
                Ks[(c4 * 4 + 2) * 260 + n] = v.z;
                Ks[(c4 * 4 + 3) * 260 + n] = v.w;
            }
            __syncthreads();

            float acc[4][8];
#pragma unroll
            for (int i = 0; i < 4; i++)
#pragma unroll
                for (int j = 0; j < 8; j++) acc[i][j] = 0.0f;

#pragma unroll 4
            for (int kk = 0; kk < 64; kk++) {
                float a[4];
#pragma unroll
                for (int i = 0; i < 4; i++) a[i] = Qs[kk * 34 + tyA + 8 * i];
                float4 b0 = *(float4*)&Ks[kk * 260 + txA * 8];
                float4 b1 = *(float4*)&Ks[kk * 260 + txA * 8 + 4];
                float bv[8] = {b0.x, b0.y, b0.z, b0.w, b1.x, b1.y, b1.z, b1.w};
#pragma unroll
                for (int i = 0; i < 4; i++)
#pragma unroll
                    for (int j = 0; j < 8; j++) acc[i][j] += a[i] * bv[j];
            }
#pragma unroll
            for (int i = 0; i < 4; i++) {
                int row = tyA + 8 * i;
                int col = nt * 256 + txA * 8;
                float4 m0, m1;
                m0.x = acc[i][0] * SCALE + mask[bi * Ss + col + 0];
                m0.y = acc[i][1] * SCALE + mask[bi * Ss + col + 1];
                m0.z = acc[i][2] * SCALE + mask[bi * Ss + col + 2];
                m0.w = acc[i][3] * SCALE + mask[bi * Ss + col + 3];
                m1.x = acc[i][4] * SCALE + mask[bi * Ss + col + 4];
                m1.y = acc[i][5] * SCALE + mask[bi * Ss + col + 5];
                m1.z = acc[i][6] * SCALE + mask[bi * Ss + col + 6];
                m1.w = acc[i][7] * SCALE + mask[bi * Ss + col + 7];
                *(float4*)&Sc[row * 1024 + col] = m0;
                *(float4*)&Sc[row * 1024 + col + 4] = m1;
            }
            __syncthreads();
        }
    }

    // ---------- Phase B: softmax + quasi gating + global prob writes ----------
    {
        const int warp = tid >> 5;
        const int lane = tid & 31;
        for (int r = warp * 4; r < warp * 4 + 4; r++) {
            float mx = -1e30f;
            for (int c = lane; c < 1024; c += 32) mx = fmaxf(mx, Sc[r * 1024 + c]);
#pragma unroll
            for (int o = 16; o > 0; o >>= 1) mx = fmaxf(mx, __shfl_xor_sync(0xffffffffu, mx, o));
            float sum = 0.0f;
            for (int c = lane; c < 1024; c += 32) {
                float e = __expf(Sc[r * 1024 + c] - mx);
                Sc[r * 1024 + c] = e;
                sum += e;
            }
#pragma unroll
            for (int o = 16; o > 0; o >>= 1) sum += __shfl_xor_sync(0xffffffffu, sum, o);
            float inv = 1.0f / sum;

            const int qrow = qb * 32 + r;
            const float lam = lam_s[r];
            const float* qs_row = &g_qsig[((size_t)(bi * Ss + qrow)) * Ss];
            const size_t rowbase = ((size_t)bh * Ss + qrow) * Ss;
            float* probs_row = out + OFF_PROBS + rowbase;
            float* quasi_row = out + OFF_QUASI + rowbase;
            float* new_row   = out + OFF_NEW + rowbase;

            for (int c4 = lane; c4 < 256; c4 += 32) {
                float4 p = *(float4*)&Sc[r * 1024 + c4 * 4];
                p.x *= inv; p.y *= inv; p.z *= inv; p.w *= inv;
                float4 qs = *(const float4*)&qs_row[c4 * 4];
                float4 qp = {lam * qs.x, lam * qs.y, lam * qs.z, lam * qs.w};
                float4 np = {p.x + qp.x, p.y + qp.y, p.z + qp.z, p.w + qp.w};
                *(float4*)&probs_row[c4 * 4] = p;
                *(float4*)&quasi_row[c4 * 4] = qp;
                *(float4*)&new_row[c4 * 4] = np;
                *(float4*)&Sc[r * 1024 + c4 * 4] = np;
            }
        }
    }
    __syncthreads();

    // ---------- Phase C: ctx[32][64] = newP[32][1024] @ V[1024][64] ----------
    {
        const int tyC = tid >> 4;
        const int txC = tid & 15;
        float acc[2][4];
#pragma unroll
        for (int i = 0; i < 2; i++)
#pragma unroll
            for (int j = 0; j < 4; j++) acc[i][j] = 0.0f;

        for (int kt = 0; kt < 16; kt++) {
#pragma unroll
            for (int i = 0; i < 4; i++) {
                int idx = tid + i * 256;
                int kk = idx >> 4, c4 = idx & 15;
                float4 v = *(const float4*)&Vg[((size_t)(kt * 64 + kk)) * 64 + c4 * 4];
                *(float4*)&Ks[kk * 68 + c4 * 4] = v;
            }
            __syncthreads();
#pragma unroll 4
            for (int kk = 0; kk < 64; kk++) {
                float a0 = Sc[tyC * 1024 + kt * 64 + kk];
                float a1 = Sc[(tyC + 16) * 1024 + kt * 64 + kk];
                float4 b4 = *(float4*)&Ks[kk * 68 + txC * 4];
                float bv[4] = {b4.x, b4.y, b4.z, b4.w};
#pragma unroll
                for (int j = 0; j < 4; j++) {
                    acc[0][j] += a0 * bv[j];
                    acc[1][j] += a1 * bv[j];
                }
            }
            __syncthreads();
        }
#pragma unroll
        for (int i = 0; i < 2; i++) {
            int qrow = qb * 32 + tyC + 16 * i;
#pragma unroll
            for (int j = 0; j < 4; j++) {
                out[((size_t)(bi * Ss + qrow)) * Dd + hi * 64 + txC * 4 + j] = acc[i][j];
            }
        }
    }
}

// ---------------- launch ----------------------------------------------------------
extern "C" void kernel_launch(void* const* d_in, const int* in_sizes, int n_in,
                              void* d_out, int out_size)
{
    (void)in_sizes; (void)n_in; (void)out_size;
    const float* hidden = (const float*)d_in[0];
    const float* mask   = (const float*)d_in[1];
    const float* ctxemb = (const float*)d_in[2];
    const float* Wq = (const float*)d_in[3];  const float* bq = (const float*)d_in[4];
    const float* Wk = (const float*)d_in[5];  const float* bk = (const float*)d_in[6];
    const float* Wv = (const float*)d_in[7];  const float* bv = (const float*)d_in[8];
    const float* Wcq = (const float*)d_in[9]; const float* bcq = (const float*)d_in[10];
    const float* Wck = (const float*)d_in[11];const float* bck = (const float*)d_in[12];
    const float* wlqc = (const float*)d_in[13];
    const float* wlqq = (const float*)d_in[14];
    const float* wlkc = (const float*)d_in[15];
    const float* wlkk = (const float*)d_in[16];
    float* out = (float*)d_out;

    // launch order chosen so attn_kernel is launch index 5 (ncu -s 5 -c 1 profiles it)
    cqck_mma<<<32, 256>>>(ctxemb, Wcq, bcq, Wck, bck);
    qsig_kernel<<<dim3(16, 16, Bb), 256>>>(mask);
    proj_mma<<<dim3(8, 32), 256>>>(hidden, Wq, bq, 0);
    proj_mma<<<dim3(8, 32), 256>>>(hidden, Wk, bk, 1);
    proj_mma<<<dim3(8, 32), 256>>>(hidden, Wv, bv, 2);

    cudaFuncSetAttribute(attn_kernel, cudaFuncAttributeMaxDynamicSharedMemorySize, ATTN_SMEM);
    attn_kernel<<<dim3(32, 64), 256, ATTN_SMEM>>>(mask, out, wlqc, wlqq, wlkc, wlkk);
}

// round 4
// speedup vs baseline: 2.2007x; 1.6530x over previous
#include <cuda_runtime.h>
#include <cuda_bf16.h>
#include <cstdint>

#define Bb 4
#define Ss 1024
#define Dd 1024
#define Hh 16
#define DHh 64
#define SCALE 0.125f

// ---------------- scratch (device globals; no allocation allowed) ----------------
__device__ float g_Q[Bb * Hh * Ss * DHh];   // [b][h][s][d]
__device__ float g_K[Bb * Hh * Ss * DHh];
__device__ float g_V[Bb * Hh * Ss * DHh];
__device__ float g_CQ[Bb * Ss * DHh];       // [b][s][d]
__device__ float g_CK[Bb * Ss * DHh];
__device__ float g_qsig[Bb * Ss * Ss];      // sigmoid quasi scores (head-invariant)

__device__ __forceinline__ float sigmoidf_(float x) { return 1.0f / (1.0f + __expf(-x)); }

__device__ __forceinline__ uint32_t f2tf(float x) {
    uint32_t r; asm("cvt.rna.tf32.f32 %0, %1;" : "=r"(r) : "f"(x)); return r;
}

__device__ __forceinline__ void mma_tf32(float* d, const uint32_t* a, const uint32_t* b) {
    asm volatile(
        "mma.sync.aligned.m16n8k8.row.col.f32.tf32.tf32.f32 "
        "{%0,%1,%2,%3}, {%4,%5,%6,%7}, {%8,%9}, {%0,%1,%2,%3};"
        : "+f"(d[0]), "+f"(d[1]), "+f"(d[2]), "+f"(d[3])
        : "r"(a[0]), "r"(a[1]), "r"(a[2]), "r"(a[3]), "r"(b[0]), "r"(b[1]));
}

// ---------------- tf32 MMA projection GEMM: [4096,1024] @ [1024,1024] -------------
__global__ __launch_bounds__(256, 2) void proj_mma(
    const float* __restrict__ A, const float* __restrict__ W,
    const float* __restrict__ bias, int which)
{
    __shared__ uint32_t As[128][36];   // [m][k], tf32 bits
    __shared__ uint32_t Bs[32][132];   // [k][n], tf32 bits
    float* out = (which == 0) ? g_Q : (which == 1) ? g_K : g_V;

    const int bm = blockIdx.y, bn = blockIdx.x;
    const int tid = threadIdx.x;
    const int warpId = tid >> 5, lane = tid & 31;
    const int warpM = warpId & 1, warpN = warpId >> 1;
    const int gr = lane >> 2;      // 0..7
    const int gc = lane & 3;       // 0..3

    float acc[4][4][4];
#pragma unroll
    for (int i = 0; i < 4; i++)
#pragma unroll
        for (int j = 0; j < 4; j++)
#pragma unroll
            for (int t = 0; t < 4; t++) acc[i][j][t] = 0.0f;

    for (int k0 = 0; k0 < 1024; k0 += 32) {
#pragma unroll
        for (int i = 0; i < 4; i++) {
            int idx = tid + i * 256;
            int r = idx >> 3, c4 = idx & 7;
            float4 v = *(const float4*)&A[(size_t)(bm * 128 + r) * 1024 + k0 + c4 * 4];
            uint4 t = {f2tf(v.x), f2tf(v.y), f2tf(v.z), f2tf(v.w)};
            *(uint4*)&As[r][c4 * 4] = t;
        }
#pragma unroll
        for (int i = 0; i < 4; i++) {
            int idx = tid + i * 256;
            int row = idx >> 5, c4 = idx & 31;
            float4 v = *(const float4*)&W[(size_t)(k0 + row) * 1024 + bn * 128 + c4 * 4];
            uint4 t = {f2tf(v.x), f2tf(v.y), f2tf(v.z), f2tf(v.w)};
            *(uint4*)&Bs[row][c4 * 4] = t;
        }
        __syncthreads();

#pragma unroll
        for (int ks = 0; ks < 4; ks++) {
            const int kb = ks * 8;
            uint32_t af[4][4];
#pragma unroll
            for (int mt = 0; mt < 4; mt++) {
                int m = warpM * 64 + mt * 16;
                af[mt][0] = As[m + gr][kb + gc];
                af[mt][1] = As[m + gr + 8][kb + gc];
                af[mt][2] = As[m + gr][kb + gc + 4];
                af[mt][3] = As[m + gr + 8][kb + gc + 4];
            }
            uint32_t bf[4][2];
#pragma unroll
            for (int nt = 0; nt < 4; nt++) {
                int n = warpN * 32 + nt * 8 + gr;
                bf[nt][0] = Bs[kb + gc][n];
                bf[nt][1] = Bs[kb + gc + 4][n];
            }
#pragma unroll
            for (int mt = 0; mt < 4; mt++)
#pragma unroll
                for (int nt = 0; nt < 4; nt++)
                    mma_tf32(acc[mt][nt], af[mt], bf[nt]);
        }
        __syncthreads();
    }

#pragma unroll
    for (int mt = 0; mt < 4; mt++) {
        int m0 = bm * 128 + warpM * 64 + mt * 16 + gr;
#pragma unroll
        for (int half = 0; half < 2; half++) {
            int m = m0 + half * 8;
            int b = m >> 10, s = m & 1023;
#pragma unroll
            for (int nt = 0; nt < 4; nt++) {
                int n = bn * 128 + warpN * 32 + nt * 8 + gc * 2;
                int h = n >> 6, d = n & 63;
                float2 v;
                v.x = acc[mt][nt][half * 2 + 0] + bias[n];
                v.y = acc[mt][nt][half * 2 + 1] + bias[n + 1];
                *(float2*)&out[(((size_t)(b * Hh + h) * Ss + s)) * 64 + d] = v;
            }
        }
    }
}

// ---------------- tf32 MMA CQ|CK GEMM: [4096,1024] @ [1024, 64|64] ----------------
__global__ __launch_bounds__(256, 2) void cqck_mma(
    const float* __restrict__ A,
    const float* __restrict__ Wcq, const float* __restrict__ bcq,
    const float* __restrict__ Wck, const float* __restrict__ bck)
{
    __shared__ uint32_t As[128][36];
    __shared__ uint32_t Bs[32][132];

    const int bm = blockIdx.x;
    const int tid = threadIdx.x;
    const int warpId = tid >> 5, lane = tid & 31;
    const int warpM = warpId & 1, warpN = warpId >> 1;
    const int gr = lane >> 2, gc = lane & 3;

    float acc[4][4][4];
#pragma unroll
    for (int i = 0; i < 4; i++)
#pragma unroll
        for (int j = 0; j < 4; j++)
#pragma unroll
            for (int t = 0; t < 4; t++) acc[i][j][t] = 0.0f;

    for (int k0 = 0; k0 < 1024; k0 += 32) {
#pragma unroll
        for (int i = 0; i < 4; i++) {
            int idx = tid + i * 256;
            int r = idx >> 3, c4 = idx & 7;
            float4 v = *(const float4*)&A[(size_t)(bm * 128 + r) * 1024 + k0 + c4 * 4];
            uint4 t = {f2tf(v.x), f2tf(v.y), f2tf(v.z), f2tf(v.w)};
            *(uint4*)&As[r][c4 * 4] = t;
        }
#pragma unroll
        for (int i = 0; i < 4; i++) {
            int idx = tid + i * 256;
            int row = idx >> 5;               // 0..31
            int c4  = idx & 31;               // 0..31
            int col = c4 * 4;
            const float* src = (col < 64)
                ? &Wcq[(size_t)(k0 + row) * 64 + col]
                : &Wck[(size_t)(k0 + row) * 64 + (col - 64)];
            float4 v = *(const float4*)src;
            uint4 t = {f2tf(v.x), f2tf(v.y), f2tf(v.z), f2tf(v.w)};
            *(uint4*)&Bs[row][col] = t;
        }
        __syncthreads();

#pragma unroll
        for (int ks = 0; ks < 4; ks++) {
            const int kb = ks * 8;
            uint32_t af[4][4];
#pragma unroll
            for (int mt = 0; mt < 4; mt++) {
                int m = warpM * 64 + mt * 16;
                af[mt][0] = As[m + gr][kb + gc];
                af[mt][1] = As[m + gr + 8][kb + gc];
                af[mt][2] = As[m + gr][kb + gc + 4];
                af[mt][3] = As[m + gr + 8][kb + gc + 4];
            }
            uint32_t bf[4][2];
#pragma unroll
            for (int nt = 0; nt < 4; nt++) {
                int n = warpN * 32 + nt * 8 + gr;
                bf[nt][0] = Bs[kb + gc][n];
                bf[nt][1] = Bs[kb + gc + 4][n];
            }
#pragma unroll
            for (int mt = 0; mt < 4; mt++)
#pragma unroll
                for (int nt = 0; nt < 4; nt++)
                    mma_tf32(acc[mt][nt], af[mt], bf[nt]);
        }
        __syncthreads();
    }

#pragma unroll
    for (int mt = 0; mt < 4; mt++) {
        int m0 = bm * 128 + warpM * 64 + mt * 16 + gr;
#pragma unroll
        for (int half = 0; half < 2; half++) {
            int m = m0 + half * 8;
#pragma unroll
            for (int nt = 0; nt < 4; nt++) {
                int n = warpN * 32 + nt * 8 + gc * 2;
                float2 v;
                if (n < 64) {
                    v.x = acc[mt][nt][half * 2 + 0] + bcq[n];
                    v.y = acc[mt][nt][half * 2 + 1] + bcq[n + 1];
                    *(float2*)&g_CQ[(size_t)m * 64 + n] = v;
                } else {
                    v.x = acc[mt][nt][half * 2 + 0] + bck[n - 64];
                    v.y = acc[mt][nt][half * 2 + 1] + bck[n - 63];
                    *(float2*)&g_CK[(size_t)m * 64 + (n - 64)] = v;
                }
            }
        }
    }
}

// ---------------- head-invariant quasi sigmoid [B,S,S] ---------------------------
__global__ __launch_bounds__(256) void qsig_kernel(const float* __restrict__ mask)
{
    __shared__ float Qs[64 * 68];
    __shared__ float Ks[64 * 68];
    const int bi = blockIdx.z, qt = blockIdx.y, kt = blockIdx.x;
    const int tid = threadIdx.x;
    const int tx = tid & 15, ty = tid >> 4;

#pragma unroll
    for (int i = 0; i < 4; i++) {
        int idx = tid + i * 256;
        int m = idx >> 4, c4 = idx & 15;
        float4 vq = *(const float4*)&g_CQ[((size_t)(bi * Ss + qt * 64 + m)) * 64 + c4 * 4];
        float4 vk = *(const float4*)&g_CK[((size_t)(bi * Ss + kt * 64 + m)) * 64 + c4 * 4];
        Qs[(c4 * 4 + 0) * 68 + m] = vq.x; Qs[(c4 * 4 + 1) * 68 + m] = vq.y;
        Qs[(c4 * 4 + 2) * 68 + m] = vq.z; Qs[(c4 * 4 + 3) * 68 + m] = vq.w;
        Ks[(c4 * 4 + 0) * 68 + m] = vk.x; Ks[(c4 * 4 + 1) * 68 + m] = vk.y;
        Ks[(c4 * 4 + 2) * 68 + m] = vk.z; Ks[(c4 * 4 + 3) * 68 + m] = vk.w;
    }
    __syncthreads();

    float acc[4][4];
#pragma unroll
    for (int i = 0; i < 4; i++)
#pragma unroll
        for (int j = 0; j < 4; j++) acc[i][j] = 0.0f;

#pragma unroll 4
    for (int d = 0; d < 64; d++) {
        float4 a4 = *(float4*)&Qs[d * 68 + ty * 4];
        float4 b4 = *(float4*)&Ks[d * 68 + tx * 4];
        float a[4] = {a4.x, a4.y, a4.z, a4.w};
        float bv[4] = {b4.x, b4.y, b4.z, b4.w};
#pragma unroll
        for (int i = 0; i < 4; i++)
#pragma unroll
            for (int j = 0; j < 4; j++) acc[i][j] += a[i] * bv[j];
    }
#pragma unroll
    for (int i = 0; i < 4; i++) {
        int qrow = qt * 64 + ty * 4 + i;
#pragma unroll
        for (int j = 0; j < 4; j++) {
            int kcol = kt * 64 + tx * 4 + j;
            float v = sigmoidf_(acc[i][j] * SCALE + mask[bi * Ss + kcol]);
            g_qsig[((size_t)(bi * Ss + qrow)) * Ss + kcol] = v;
        }
    }
}

// ---------------- fused attention: tf32 MMA phases A & C --------------------------
// smem layout (words):
//   Sc   [32][1028]  fp32 scores / tf32 newP bits   (32896)
//   Qtf  [32][68]    tf32 Q                          (2176)
//   Ks   [256][68]   tf32 K chunk (reused: Vs [64][72])   (17408)
//   lam  [32]
#define SC_STRIDE 1028
#define ATTN_WORDS (32 * SC_STRIDE + 32 * 68 + 256 * 68 + 32)
#define ATTN_SMEM (ATTN_WORDS * 4)

__global__ __launch_bounds__(256, 1) void attn_kernel(
    const float* __restrict__ mask, float* __restrict__ out,
    const float* __restrict__ wlqc, const float* __restrict__ wlqq,
    const float* __restrict__ wlkc, const float* __restrict__ wlkk)
{
    extern __shared__ float sm[];
    float* Sc = sm;                                  // 32*1028
    uint32_t* Scu = (uint32_t*)Sc;
    uint32_t* Qtf = (uint32_t*)(Sc + 32 * SC_STRIDE);// 32*68
    uint32_t* Ks  = Qtf + 32 * 68;                   // 256*68 (reused as Vs 64*72)
    uint32_t* Vs  = Ks;
    float* lam_s  = (float*)(Ks + 256 * 68);         // 32

    const int qb = blockIdx.x;             // 0..31
    const int bh = blockIdx.y;             // b*H + h
    const int bi = bh >> 4;
    const int hi = bh & 15;
    const int tid = threadIdx.x;
    const int w = tid >> 5, lane = tid & 31;
    const int gr = lane >> 2, gc = lane & 3;

    const float* Qg = &g_Q[((size_t)bh * Ss + qb * 32) * 64];
    const float* Kg = &g_K[(size_t)bh * Ss * 64];
    const float* Vg = &g_V[(size_t)bh * Ss * 64];

    const size_t OFF_NEW   = (size_t)Bb * Ss * Dd;
    const size_t OFF_PROBS = OFF_NEW + (size_t)Bb * Hh * Ss * Ss;
    const size_t OFF_QUASI = OFF_PROBS + (size_t)Bb * Hh * Ss * Ss;

    // load Q tile [32][64] -> Qtf[m][k] (tf32, row-major, stride 68)
#pragma unroll
    for (int i = 0; i < 2; i++) {
        int idx = tid + i * 256;       // 0..511
        int m = idx >> 4, c4 = idx & 15;
        float4 v = *(const float4*)&Qg[(size_t)m * 64 + c4 * 4];
        uint4 t = {f2tf(v.x), f2tf(v.y), f2tf(v.z), f2tf(v.w)};
        *(uint4*)&Qtf[m * 68 + c4 * 4] = t;
    }

    // inline lambda_context for the 32 query rows
    {
        int r = tid >> 3;          // 0..31
        int j = tid & 7;           // 0..7
        int qrow = qb * 32 + r;
        const float* cq = &g_CQ[((size_t)(bi * Ss + qrow)) * 64];
        const float* ck = &g_CK[((size_t)(bi * Ss + qrow)) * 64];
        const float* qp = &Qg[(size_t)r * 64];
        const float* kp = &Kg[((size_t)(qb * 32 + r)) * 64];
        float sq = 0.f, sk = 0.f;
#pragma unroll
        for (int d0 = 0; d0 < 8; d0++) {
            int d = j * 8 + d0;
            sq += cq[d] * wlqc[d] + qp[d] * wlqq[d];
            sk += ck[d] * wlkc[d] + kp[d] * wlkk[d];
        }
#pragma unroll
        for (int o = 4; o > 0; o >>= 1) {
            sq += __shfl_xor_sync(0xffffffffu, sq, o);
            sk += __shfl_xor_sync(0xffffffffu, sk, o);
        }
        if (j == 0) lam_s[r] = 1.0f - sigmoidf_(sq) - sigmoidf_(sk);
    }

    // ---------- Phase A (MMA): Sc[32][1024] = Q @ K^T * scale + mask ----------
    for (int nt = 0; nt < 4; nt++) {
        // K chunk 256 rows x 64 d -> Ks[n][d] tf32
#pragma unroll
        for (int i = 0; i < 16; i++) {
            int idx = tid + i * 256;          // 0..4095
            int n = idx >> 4, c4 = idx & 15;
            float4 v = *(const float4*)&Kg[((size_t)(nt * 256 + n)) * 64 + c4 * 4];
            uint4 t = {f2tf(v.x), f2tf(v.y), f2tf(v.z), f2tf(v.w)};
            *(uint4*)&Ks[n * 68 + c4 * 4] = t;
        }
        __syncthreads();

        float acc[2][4][4];
#pragma unroll
        for (int m = 0; m < 2; m++)
#pragma unroll
            for (int t = 0; t < 4; t++)
#pragma unroll
                for (int e = 0; e < 4; e++) acc[m][t][e] = 0.0f;

#pragma unroll
        for (int ks = 0; ks < 8; ks++) {
            const int kb = ks * 8;
            uint32_t af[2][4];
#pragma unroll
            for (int m = 0; m < 2; m++) {
                int m0 = m * 16;
                af[m][0] = Qtf[(m0 + gr) * 68 + kb + gc];
                af[m][1] = Qtf[(m0 + gr + 8) * 68 + kb + gc];
                af[m][2] = Qtf[(m0 + gr) * 68 + kb + gc + 4];
                af[m][3] = Qtf[(m0 + gr + 8) * 68 + kb + gc + 4];
            }
            uint32_t bf[4][2];
#pragma unroll
            for (int t = 0; t < 4; t++) {
                int n0 = w * 32 + t * 8;
                bf[t][0] = Ks[(n0 + gr) * 68 + kb + gc];
                bf[t][1] = Ks[(n0 + gr) * 68 + kb + gc + 4];
            }
#pragma unroll
            for (int m = 0; m < 2; m++)
#pragma unroll
                for (int t = 0; t < 4; t++)
                    mma_tf32(acc[m][t], af[m], bf[t]);
        }

        // write scores with scale + mask
#pragma unroll
        for (int m = 0; m < 2; m++) {
            int row0 = m * 16 + gr;
#pragma unroll
            for (int t = 0; t < 4; t++) {
                int col = nt * 256 + w * 32 + t * 8 + gc * 2;
                float mk0 = mask[bi * Ss + col];
                float mk1 = mask[bi * Ss + col + 1];
                float2 v0, v1;
                v0.x = acc[m][t][0] * SCALE + mk0;
                v0.y = acc[m][t][1] * SCALE + mk1;
                v1.x = acc[m][t][2] * SCALE + mk0;
                v1.y = acc[m][t][3] * SCALE + mk1;
                *(float2*)&Sc[row0 * SC_STRIDE + col] = v0;
                *(float2*)&Sc[(row0 + 8) * SC_STRIDE + col] = v1;
            }
        }
        __syncthreads();
    }

    // ---------- Phase B: softmax + quasi gating + global prob writes ----------
    {
        for (int r = w * 4; r < w * 4 + 4; r++) {
            float mx = -1e30f;
            for (int c = lane; c < 1024; c += 32) mx = fmaxf(mx, Sc[r * SC_STRIDE + c]);
#pragma unroll
            for (int o = 16; o > 0; o >>= 1) mx = fmaxf(mx, __shfl_xor_sync(0xffffffffu, mx, o));
            float sum = 0.0f;
            for (int c = lane; c < 1024; c += 32) {
                float e = __expf(Sc[r * SC_STRIDE + c] - mx);
                Sc[r * SC_STRIDE + c] = e;
                sum += e;
            }
#pragma unroll
            for (int o = 16; o > 0; o >>= 1) sum += __shfl_xor_sync(0xffffffffu, sum, o);
            float inv = 1.0f / sum;

            const int qrow = qb * 32 + r;
            const float lam = lam_s[r];
            const float* qs_row = &g_qsig[((size_t)(bi * Ss + qrow)) * Ss];
            const size_t rowbase = ((size_t)bh * Ss + qrow) * Ss;
            float* probs_row = out + OFF_PROBS + rowbase;
            float* quasi_row = out + OFF_QUASI + rowbase;
            float* new_row   = out + OFF_NEW + rowbase;

            for (int c4 = lane; c4 < 256; c4 += 32) {
                float4 p = *(float4*)&Sc[r * SC_STRIDE + c4 * 4];
                p.x *= inv; p.y *= inv; p.z *= inv; p.w *= inv;
                float4 qs = *(const float4*)&qs_row[c4 * 4];
                float4 qp = {lam * qs.x, lam * qs.y, lam * qs.z, lam * qs.w};
                float4 np = {p.x + qp.x, p.y + qp.y, p.z + qp.z, p.w + qp.w};
                *(float4*)&probs_row[c4 * 4] = p;
                *(float4*)&quasi_row[c4 * 4] = qp;
                *(float4*)&new_row[c4 * 4] = np;
                // stash tf32 bits of newP back into Sc for phase C
                uint4 tp = {f2tf(np.x), f2tf(np.y), f2tf(np.z), f2tf(np.w)};
                *(uint4*)&Scu[r * SC_STRIDE + c4 * 4] = tp;
            }
        }
    }
    __syncthreads();

    // ---------- Phase C (MMA): ctx[32][64] = newP[32][1024] @ V[1024][64] ----------
    {
        float acc[2][4];
#pragma unroll
        for (int m = 0; m < 2; m++)
#pragma unroll
            for (int e = 0; e < 4; e++) acc[m][e] = 0.0f;

        for (int kt = 0; kt < 16; kt++) {
            // V chunk [64 kpos][64 d] -> Vs[k][d] tf32, stride 72
#pragma unroll
            for (int i = 0; i < 4; i++) {
                int idx = tid + i * 256;          // 0..1023
                int kk = idx >> 4, c4 = idx & 15;
                float4 v = *(const float4*)&Vg[((size_t)(kt * 64 + kk)) * 64 + c4 * 4];
                uint4 t = {f2tf(v.x), f2tf(v.y), f2tf(v.z), f2tf(v.w)};
                *(uint4*)&Vs[kk * 72 + c4 * 4] = t;
            }
            __syncthreads();

#pragma unroll
            for (int ks = 0; ks < 8; ks++) {
                int k0 = kt * 64 + ks * 8;
                uint32_t af[2][4];
#pragma unroll
                for (int m = 0; m < 2; m++) {
                    int m0 = m * 16;
                    af[m][0] = Scu[(m0 + gr) * SC_STRIDE + k0 + gc];
                    af[m][1] = Scu[(m0 + gr + 8) * SC_STRIDE + k0 + gc];
                    af[m][2] = Scu[(m0 + gr) * SC_STRIDE + k0 + gc + 4];
                    af[m][3] = Scu[(m0 + gr + 8) * SC_STRIDE + k0 + gc + 4];
                }
                uint32_t bf[2];
                int n0 = w * 8;
                bf[0] = Vs[(ks * 8 + gc) * 72 + n0 + gr];
                bf[1] = Vs[(ks * 8 + gc + 4) * 72 + n0 + gr];
                mma_tf32(acc[0], af[0], bf);
                mma_tf32(acc[1], af[1], bf);
            }
            __syncthreads();
        }

        // epilogue: ctx writes
#pragma unroll
        for (int m = 0; m < 2; m++) {
            int row0 = qb * 32 + m * 16 + gr;
            int col = hi * 64 + w * 8 + gc * 2;
            float2 v0 = {acc[m][0], acc[m][1]};
            float2 v1 = {acc[m][2], acc[m][3]};
            *(float2*)&out[((size_t)(bi * Ss + row0)) * Dd + col] = v0;
            *(float2*)&out[((size_t)(bi * Ss + row0 + 8)) * Dd + col] = v1;
        }
    }
}

// ---------------- launch ----------------------------------------------------------
extern "C" void kernel_launch(void* const* d_in, const int* in_sizes, int n_in,
                              void* d_out, int out_size)
{
    (void)in_sizes; (void)n_in; (void)out_size;
    const float* hidden = (const float*)d_in[0];
    const float* mask   = (const float*)d_in[1];
    const float* ctxemb = (const float*)d_in[2];
    const float* Wq = (const float*)d_in[3];  const float* bq = (const float*)d_in[4];
    const float* Wk = (const float*)d_in[5];  const float* bk = (const float*)d_in[6];
    const float* Wv = (const float*)d_in[7];  const float* bv = (const float*)d_in[8];
    const float* Wcq = (const float*)d_in[9]; const float* bcq = (const float*)d_in[10];
    const float* Wck = (const float*)d_in[11];const float* bck = (const float*)d_in[12];
    const float* wlqc = (const float*)d_in[13];
    const float* wlqq = (const float*)d_in[14];
    const float* wlkc = (const float*)d_in[15];
    const float* wlkk = (const float*)d_in[16];
    float* out = (float*)d_out;

    // launch order: attn_kernel is launch index 5 (ncu -s 5 -c 1 profiles it)
    cqck_mma<<<32, 256>>>(ctxemb, Wcq, bcq, Wck, bck);
    qsig_kernel<<<dim3(16, 16, Bb), 256>>>(mask);
    proj_mma<<<dim3(8, 32), 256>>>(hidden, Wq, bq, 0);
    proj_mma<<<dim3(8, 32), 256>>>(hidden, Wk, bk, 1);
    proj_mma<<<dim3(8, 32), 256>>>(hidden, Wv, bv, 2);

    cudaFuncSetAttribute(attn_kernel, cudaFuncAttributeMaxDynamicSharedMemorySize, ATTN_SMEM);
    attn_kernel<<<dim3(32, 64), 256, ATTN_SMEM>>>(mask, out, wlqc, wlqq, wlkc, wlkk);
}

// round 5
// speedup vs baseline: 2.5364x; 1.1525x over previous
#include <cuda_runtime.h>
#include <cuda_bf16.h>
#include <cstdint>

#define Bb 4
#define Ss 1024
#define Dd 1024
#define Hh 16
#define DHh 64
#define SCALE 0.125f

// ---------------- scratch (device globals; no allocation allowed) ----------------
__device__ float g_Q[Bb * Hh * Ss * DHh];     // fp32 [b][h][s][d] (lam needs Q,K fp32)
__device__ float g_K[Bb * Hh * Ss * DHh];
__device__ uint32_t g_Qt[Bb * Hh * Ss * DHh]; // tf32 bits
__device__ uint32_t g_Kt[Bb * Hh * Ss * DHh];
__device__ uint32_t g_Vt[Bb * Hh * Ss * DHh];
__device__ float g_CQ[Bb * Ss * DHh];
__device__ float g_CK[Bb * Ss * DHh];
__device__ float g_qsig[Bb * Ss * Ss];        // sigmoid quasi scores (head-invariant)
__device__ uint32_t g_Atf[Bb * Ss * Dd];      // tf32 hidden
__device__ uint32_t g_Wtf[3 * Dd * Dd];       // tf32 Wq|Wk|Wv

__device__ __forceinline__ float sigmoidf_(float x) { return 1.0f / (1.0f + __expf(-x)); }

__device__ __forceinline__ uint32_t f2tf(float x) {
    uint32_t r; asm("cvt.rna.tf32.f32 %0, %1;" : "=r"(r) : "f"(x)); return r;
}

__device__ __forceinline__ void mma_tf32(float* d, const uint32_t* a, const uint32_t* b) {
    asm volatile(
        "mma.sync.aligned.m16n8k8.row.col.f32.tf32.tf32.f32 "
        "{%0,%1,%2,%3}, {%4,%5,%6,%7}, {%8,%9}, {%0,%1,%2,%3};"
        : "+f"(d[0]), "+f"(d[1]), "+f"(d[2]), "+f"(d[3])
        : "r"(a[0]), "r"(a[1]), "r"(a[2]), "r"(a[3]), "r"(b[0]), "r"(b[1]));
}

__device__ __forceinline__ void cpa16(void* dst, const void* src) {
    uint32_t sa = (uint32_t)__cvta_generic_to_shared(dst);
    asm volatile("cp.async.cg.shared.global [%0], [%1], 16;" :: "r"(sa), "l"(src));
}

// ---------------- kernel 0: convert inputs to tf32 + CQ/CK GEMM -------------------
__global__ __launch_bounds__(256, 2) void cqck_conv(
    const float* __restrict__ A,      // context_embedded
    const float* __restrict__ hidden,
    const float* __restrict__ Wq, const float* __restrict__ Wk, const float* __restrict__ Wv,
    const float* __restrict__ Wcq, const float* __restrict__ bcq,
    const float* __restrict__ Wck, const float* __restrict__ bck)
{
    // ---- grid-stride tf32 conversion (hidden + 3 weight matrices) ----
    {
        const int NT = 32 * 256;
        int t0 = blockIdx.x * 256 + threadIdx.x;
        const float4* hs = (const float4*)hidden;
        uint4* ad = (uint4*)g_Atf;
        for (int i = t0; i < (Bb * Ss * Dd) / 4; i += NT) {
            float4 v = hs[i];
            uint4 t = {f2tf(v.x), f2tf(v.y), f2tf(v.z), f2tf(v.w)};
            ad[i] = t;
        }
        const float* Ws[3] = {Wq, Wk, Wv};
        for (int wsel = 0; wsel < 3; wsel++) {
            const float4* s = (const float4*)Ws[wsel];
            uint4* d = (uint4*)(g_Wtf + wsel * (Dd * Dd));
            for (int i = t0; i < (Dd * Dd) / 4; i += NT) {
                float4 v = s[i];
                uint4 t = {f2tf(v.x), f2tf(v.y), f2tf(v.z), f2tf(v.w)};
                d[i] = t;
            }
        }
    }

    // ---- CQ|CK tf32 MMA GEMM ----
    __shared__ uint32_t As[128][36];
    __shared__ uint32_t Bs[32][132];

    const int bm = blockIdx.x;
    const int tid = threadIdx.x;
    const int warpId = tid >> 5, lane = tid & 31;
    const int warpM = warpId & 1, warpN = warpId >> 1;
    const int gr = lane >> 2, gc = lane & 3;

    float acc[4][4][4];
#pragma unroll
    for (int i = 0; i < 4; i++)
#pragma unroll
        for (int j = 0; j < 4; j++)
#pragma unroll
            for (int t = 0; t < 4; t++) acc[i][j][t] = 0.0f;

    for (int k0 = 0; k0 < 1024; k0 += 32) {
#pragma unroll
        for (int i = 0; i < 4; i++) {
            int idx = tid + i * 256;
            int r = idx >> 3, c4 = idx & 7;
            float4 v = *(const float4*)&A[(size_t)(bm * 128 + r) * 1024 + k0 + c4 * 4];
            uint4 t = {f2tf(v.x), f2tf(v.y), f2tf(v.z), f2tf(v.w)};
            *(uint4*)&As[r][c4 * 4] = t;
        }
#pragma unroll
        for (int i = 0; i < 4; i++) {
            int idx = tid + i * 256;
            int row = idx >> 5;
            int c4  = idx & 31;
            int col = c4 * 4;
            const float* src = (col < 64)
                ? &Wcq[(size_t)(k0 + row) * 64 + col]
                : &Wck[(size_t)(k0 + row) * 64 + (col - 64)];
            float4 v = *(const float4*)src;
            uint4 t = {f2tf(v.x), f2tf(v.y), f2tf(v.z), f2tf(v.w)};
            *(uint4*)&Bs[row][col] = t;
        }
        __syncthreads();

#pragma unroll
        for (int ks = 0; ks < 4; ks++) {
            const int kb = ks * 8;
            uint32_t af[4][4];
#pragma unroll
            for (int mt = 0; mt < 4; mt++) {
                int m = warpM * 64 + mt * 16;
                af[mt][0] = As[m + gr][kb + gc];
                af[mt][1] = As[m + gr + 8][kb + gc];
                af[mt][2] = As[m + gr][kb + gc + 4];
                af[mt][3] = As[m + gr + 8][kb + gc + 4];
            }
            uint32_t bf[4][2];
#pragma unroll
            for (int nt = 0; nt < 4; nt++) {
                int n = warpN * 32 + nt * 8 + gr;
                bf[nt][0] = Bs[kb + gc][n];
                bf[nt][1] = Bs[kb + gc + 4][n];
            }
#pragma unroll
            for (int mt = 0; mt < 4; mt++)
#pragma unroll
                for (int nt = 0; nt < 4; nt++)
                    mma_tf32(acc[mt][nt], af[mt], bf[nt]);
        }
        __syncthreads();
    }

#pragma unroll
    for (int mt = 0; mt < 4; mt++) {
        int m0 = bm * 128 + warpM * 64 + mt * 16 + gr;
#pragma unroll
        for (int half = 0; half < 2; half++) {
            int m = m0 + half * 8;
#pragma unroll
            for (int nt = 0; nt < 4; nt++) {
                int n = warpN * 32 + nt * 8 + gc * 2;
                float2 v;
                if (n < 64) {
                    v.x = acc[mt][nt][half * 2 + 0] + bcq[n];
                    v.y = acc[mt][nt][half * 2 + 1] + bcq[n + 1];
                    *(float2*)&g_CQ[(size_t)m * 64 + n] = v;
                } else {
                    v.x = acc[mt][nt][half * 2 + 0] + bck[n - 64];
                    v.y = acc[mt][nt][half * 2 + 1] + bck[n - 63];
                    *(float2*)&g_CK[(size_t)m * 64 + (n - 64)] = v;
                }
            }
        }
    }
}

// ---------------- kernel 1: head-invariant quasi sigmoid [B,S,S] ------------------
__global__ __launch_bounds__(256) void qsig_kernel(const float* __restrict__ mask)
{
    __shared__ float Qs[64 * 68];
    __shared__ float Ks[64 * 68];
    const int bi = blockIdx.z, qt = blockIdx.y, kt = blockIdx.x;
    const int tid = threadIdx.x;
    const int tx = tid & 15, ty = tid >> 4;

#pragma unroll
    for (int i = 0; i < 4; i++) {
        int idx = tid + i * 256;
        int m = idx >> 4, c4 = idx & 15;
        float4 vq = *(const float4*)&g_CQ[((size_t)(bi * Ss + qt * 64 + m)) * 64 + c4 * 4];
        float4 vk = *(const float4*)&g_CK[((size_t)(bi * Ss + kt * 64 + m)) * 64 + c4 * 4];
        Qs[(c4 * 4 + 0) * 68 + m] = vq.x; Qs[(c4 * 4 + 1) * 68 + m] = vq.y;
        Qs[(c4 * 4 + 2) * 68 + m] = vq.z; Qs[(c4 * 4 + 3) * 68 + m] = vq.w;
        Ks[(c4 * 4 + 0) * 68 + m] = vk.x; Ks[(c4 * 4 + 1) * 68 + m] = vk.y;
        Ks[(c4 * 4 + 2) * 68 + m] = vk.z; Ks[(c4 * 4 + 3) * 68 + m] = vk.w;
    }
    __syncthreads();

    float acc[4][4];
#pragma unroll
    for (int i = 0; i < 4; i++)
#pragma unroll
        for (int j = 0; j < 4; j++) acc[i][j] = 0.0f;

#pragma unroll 4
    for (int d = 0; d < 64; d++) {
        float4 a4 = *(float4*)&Qs[d * 68 + ty * 4];
        float4 b4 = *(float4*)&Ks[d * 68 + tx * 4];
        float a[4] = {a4.x, a4.y, a4.z, a4.w};
        float bv[4] = {b4.x, b4.y, b4.z, b4.w};
#pragma unroll
        for (int i = 0; i < 4; i++)
#pragma unroll
            for (int j = 0; j < 4; j++) acc[i][j] += a[i] * bv[j];
    }
#pragma unroll
    for (int i = 0; i < 4; i++) {
        int qrow = qt * 64 + ty * 4 + i;
#pragma unroll
        for (int j = 0; j < 4; j++) {
            int kcol = kt * 64 + tx * 4 + j;
            float v = sigmoidf_(acc[i][j] * SCALE + mask[bi * Ss + kcol]);
            g_qsig[((size_t)(bi * Ss + qrow)) * Ss + kcol] = v;
        }
    }
}

// ---------------- kernel 2: pipelined tf32 projection GEMM (QKV in one grid) ------
// grid (8, 32, 3): z = which. cp.async 2-stage, BK=32.
#define PROJ_SMEM ((2 * 128 * 36 + 2 * 32 * 132) * 4)

__global__ __launch_bounds__(256, 2) void proj_mma(
    const float* __restrict__ bq, const float* __restrict__ bk, const float* __restrict__ bv)
{
    extern __shared__ uint32_t ps[];
    uint32_t* As = ps;                 // 2 stages: [st][128][36]
    uint32_t* Bs = ps + 2 * 128 * 36;  // 2 stages: [st][32][132]

    const int which = blockIdx.z;
    const uint32_t* Wtf = g_Wtf + which * (Dd * Dd);
    const float* bias = (which == 0) ? bq : (which == 1) ? bk : bv;
    uint32_t* outt = (which == 0) ? g_Qt : (which == 1) ? g_Kt : g_Vt;
    float* outf = (which == 0) ? g_Q : g_K;   // used only when which < 2

    const int bm = blockIdx.y, bn = blockIdx.x;
    const int tid = threadIdx.x;
    const int warpId = tid >> 5, lane = tid & 31;
    const int warpM = warpId & 1, warpN = warpId >> 1;
    const int gr = lane >> 2, gc = lane & 3;

    // per-thread load coordinates
    const int ar = tid >> 1;                  // unused pattern; we use idx loops below

    float acc[4][4][4];
#pragma unroll
    for (int i = 0; i < 4; i++)
#pragma unroll
        for (int j = 0; j < 4; j++)
#pragma unroll
            for (int t = 0; t < 4; t++) acc[i][j][t] = 0.0f;

    auto issue = [&](int st, int k0) {
#pragma unroll
        for (int i = 0; i < 4; i++) {
            int idx = tid + i * 256;
            int r = idx >> 3, c4 = idx & 7;
            cpa16(&As[st * 4608 + r * 36 + c4 * 4],
                  &g_Atf[(size_t)(bm * 128 + r) * 1024 + k0 + c4 * 4]);
        }
#pragma unroll
        for (int i = 0; i < 4; i++) {
            int idx = tid + i * 256;
            int row = idx >> 5, c4 = idx & 31;
            cpa16(&Bs[st * 4224 + row * 132 + c4 * 4],
                  &Wtf[(size_t)(k0 + row) * 1024 + bn * 128 + c4 * 4]);
        }
        asm volatile("cp.async.commit_group;");
    };

    issue(0, 0);

    for (int kt = 0; kt < 32; kt++) {
        if (kt < 31) {
            issue((kt + 1) & 1, (kt + 1) * 32);
            asm volatile("cp.async.wait_group 1;");
        } else {
            asm volatile("cp.async.wait_group 0;");
        }
        __syncthreads();

        const uint32_t* Ast = As + (kt & 1) * 4608;
        const uint32_t* Bst = Bs + (kt & 1) * 4224;
#pragma unroll
        for (int ks = 0; ks < 4; ks++) {
            const int kb = ks * 8;
            uint32_t af[4][4];
#pragma unroll
            for (int mt = 0; mt < 4; mt++) {
                int m = warpM * 64 + mt * 16;
                af[mt][0] = Ast[(m + gr) * 36 + kb + gc];
                af[mt][1] = Ast[(m + gr + 8) * 36 + kb + gc];
                af[mt][2] = Ast[(m + gr) * 36 + kb + gc + 4];
                af[mt][3] = Ast[(m + gr + 8) * 36 + kb + gc + 4];
            }
            uint32_t bf[4][2];
#pragma unroll
            for (int nt = 0; nt < 4; nt++) {
                int n = warpN * 32 + nt * 8 + gr;
                bf[nt][0] = Bst[(kb + gc) * 132 + n];
                bf[nt][1] = Bst[(kb + gc + 4) * 132 + n];
            }
#pragma unroll
            for (int mt = 0; mt < 4; mt++)
#pragma unroll
                for (int nt = 0; nt < 4; nt++)
                    mma_tf32(acc[mt][nt], af[mt], bf[nt]);
        }
        __syncthreads();
    }

    // epilogue: scatter to [B,H,S,DH]; fp32 (Q,K only) + tf32 bits (all)
#pragma unroll
    for (int mt = 0; mt < 4; mt++) {
        int m0 = bm * 128 + warpM * 64 + mt * 16 + gr;
#pragma unroll
        for (int half = 0; half < 2; half++) {
            int m = m0 + half * 8;
            int b = m >> 10, s = m & 1023;
#pragma unroll
            for (int nt = 0; nt < 4; nt++) {
                int n = bn * 128 + warpN * 32 + nt * 8 + gc * 2;
                int h = n >> 6, d = n & 63;
                size_t o = (((size_t)(b * Hh + h) * Ss + s)) * 64 + d;
                float2 v;
                v.x = acc[mt][nt][half * 2 + 0] + bias[n];
                v.y = acc[mt][nt][half * 2 + 1] + bias[n + 1];
                if (which < 2) *(float2*)&outf[o] = v;
                uint2 tv = {f2tf(v.x), f2tf(v.y)};
                *(uint2*)&outt[o] = tv;
            }
        }
    }
}

// ---------------- kernel 3: attention phases A+B (512 threads) --------------------
// smem: Sc[32][1028] + Qtf[32][68] + Ks[256][68] + lam[32]
#define SC_STRIDE 1028
#define ATTN_WORDS (32 * SC_STRIDE + 32 * 68 + 256 * 68 + 32)
#define ATTN_SMEM (ATTN_WORDS * 4)

__global__ __launch_bounds__(512, 1) void attn_ab(
    const float* __restrict__ mask, float* __restrict__ out,
    const float* __restrict__ wlqc, const float* __restrict__ wlqq,
    const float* __restrict__ wlkc, const float* __restrict__ wlkk)
{
    extern __shared__ float sm[];
    float* Sc = sm;                                   // 32*1028
    uint32_t* Qtf = (uint32_t*)(Sc + 32 * SC_STRIDE); // 32*68
    uint32_t* Ks  = Qtf + 32 * 68;                    // 256*68
    float* lam_s  = (float*)(Ks + 256 * 68);          // 32

    const int qb = blockIdx.x;
    const int bh = blockIdx.y;
    const int bi = bh >> 4;
    const int tid = threadIdx.x;
    const int w = tid >> 5, lane = tid & 31;
    const int gr = lane >> 2, gc = lane & 3;
    const int wm = w >> 3, wn = w & 7;     // 2 x 8 warp grid

    const uint32_t* Qtg = &g_Qt[((size_t)bh * Ss + qb * 32) * 64];
    const uint32_t* Ktg = &g_Kt[(size_t)bh * Ss * 64];

    const size_t OFF_NEW   = (size_t)Bb * Ss * Dd;
    const size_t OFF_PROBS = OFF_NEW + (size_t)Bb * Hh * Ss * Ss;
    const size_t OFF_QUASI = OFF_PROBS + (size_t)Bb * Hh * Ss * Ss;

    // load Q tile [32][64] tf32 bits
    {
        int m = tid >> 4, c4 = tid & 15;
        uint4 v = *(const uint4*)&Qtg[(size_t)m * 64 + c4 * 4];
        *(uint4*)&Qtf[m * 68 + c4 * 4] = v;
    }

    // inline lambda_context (fp32 Q/K)
    {
        int r = tid >> 4;          // 0..31
        int j = tid & 15;          // 0..15
        int qrow = qb * 32 + r;
        const float* cq = &g_CQ[((size_t)(bi * Ss + qrow)) * 64];
        const float* ck = &g_CK[((size_t)(bi * Ss + qrow)) * 64];
        const float* qp = &g_Q[((size_t)bh * Ss + qrow) * 64];
        const float* kp = &g_K[((size_t)bh * Ss + qrow) * 64];
        float sq = 0.f, sk = 0.f;
#pragma unroll
        for (int d0 = 0; d0 < 4; d0++) {
            int d = j * 4 + d0;
            sq += cq[d] * wlqc[d] + qp[d] * wlqq[d];
            sk += ck[d] * wlkc[d] + kp[d] * wlkk[d];
        }
#pragma unroll
        for (int o = 8; o > 0; o >>= 1) {
            sq += __shfl_xor_sync(0xffffffffu, sq, o);
            sk += __shfl_xor_sync(0xffffffffu, sk, o);
        }
        if (j == 0) lam_s[r] = 1.0f - sigmoidf_(sq) - sigmoidf_(sk);
    }

    // ---------- Phase A (MMA): Sc[32][1024] = Q @ K^T * scale + mask ----------
    for (int nt = 0; nt < 4; nt++) {
#pragma unroll
        for (int i = 0; i < 8; i++) {
            int idx = tid + i * 512;          // 0..4095
            int n = idx >> 4, c4 = idx & 15;
            uint4 v = *(const uint4*)&Ktg[((size_t)(nt * 256 + n)) * 64 + c4 * 4];
            *(uint4*)&Ks[n * 68 + c4 * 4] = v;
        }
        __syncthreads();

        float acc[4][4];
#pragma unroll
        for (int t = 0; t < 4; t++)
#pragma unroll
            for (int e = 0; e < 4; e++) acc[t][e] = 0.0f;

#pragma unroll
        for (int ks = 0; ks < 8; ks++) {
            const int kb = ks * 8;
            uint32_t af[4];
            int m0 = wm * 16;
            af[0] = Qtf[(m0 + gr) * 68 + kb + gc];
            af[1] = Qtf[(m0 + gr + 8) * 68 + kb + gc];
            af[2] = Qtf[(m0 + gr) * 68 + kb + gc + 4];
            af[3] = Qtf[(m0 + gr + 8) * 68 + kb + gc + 4];
#pragma unroll
            for (int t = 0; t < 4; t++) {
                int n0 = wn * 32 + t * 8;
                uint32_t bf[2];
                bf[0] = Ks[(n0 + gr) * 68 + kb + gc];
                bf[1] = Ks[(n0 + gr) * 68 + kb + gc + 4];
                mma_tf32(acc[t], af, bf);
            }
        }

#pragma unroll
        for (int t = 0; t < 4; t++) {
            int row0 = wm * 16 + gr;
            int col = nt * 256 + wn * 32 + t * 8 + gc * 2;
            float mk0 = mask[bi * Ss + col];
            float mk1 = mask[bi * Ss + col + 1];
            float2 v0 = {acc[t][0] * SCALE + mk0, acc[t][1] * SCALE + mk1};
            float2 v1 = {acc[t][2] * SCALE + mk0, acc[t][3] * SCALE + mk1};
            *(float2*)&Sc[row0 * SC_STRIDE + col] = v0;
            *(float2*)&Sc[(row0 + 8) * SC_STRIDE + col] = v1;
        }
        __syncthreads();
    }

    // ---------- Phase B: softmax + quasi gating + prob writes ----------
    {
        for (int r = w * 2; r < w * 2 + 2; r++) {
            float mx = -1e30f;
            for (int c = lane; c < 1024; c += 32) mx = fmaxf(mx, Sc[r * SC_STRIDE + c]);
#pragma unroll
            for (int o = 16; o > 0; o >>= 1) mx = fmaxf(mx, __shfl_xor_sync(0xffffffffu, mx, o));
            float sum = 0.0f;
            for (int c = lane; c < 1024; c += 32) {
                float e = __expf(Sc[r * SC_STRIDE + c] - mx);
                Sc[r * SC_STRIDE + c] = e;
                sum += e;
            }
#pragma unroll
            for (int o = 16; o > 0; o >>= 1) sum += __shfl_xor_sync(0xffffffffu, sum, o);
            float inv = 1.0f / sum;

            const int qrow = qb * 32 + r;
            const float lam = lam_s[r];
            const float* qs_row = &g_qsig[((size_t)(bi * Ss + qrow)) * Ss];
            const size_t rowbase = ((size_t)bh * Ss + qrow) * Ss;
            float* probs_row = out + OFF_PROBS + rowbase;
            float* quasi_row = out + OFF_QUASI + rowbase;
            float* new_row   = out + OFF_NEW + rowbase;

            for (int c4 = lane; c4 < 256; c4 += 32) {
                float4 p = *(float4*)&Sc[r * SC_STRIDE + c4 * 4];
                p.x *= inv; p.y *= inv; p.z *= inv; p.w *= inv;
                float4 qs = *(const float4*)&qs_row[c4 * 4];
                float4 qp = {lam * qs.x, lam * qs.y, lam * qs.z, lam * qs.w};
                float4 np = {p.x + qp.x, p.y + qp.y, p.z + qp.z, p.w + qp.w};
                *(float4*)&probs_row[c4 * 4] = p;
                *(float4*)&quasi_row[c4 * 4] = qp;
                *(float4*)&new_row[c4 * 4] = np;
            }
        }
    }
}

// ---------------- kernel 4: ctx = newP @ V (batched tf32 GEMM) --------------------
// grid (8, 64): 128 q-rows x 64 d per block; BK=64; 256 threads (4M x 2N warps).
#define PV_SMEM ((128 * 68 + 64 * 72) * 4)

__global__ __launch_bounds__(256) void pv_gemm(float* __restrict__ out)
{
    extern __shared__ uint32_t pvs[];
    uint32_t* Ps = pvs;               // [128][68]
    uint32_t* Vs = pvs + 128 * 68;    // [64][72]

    const int qt = blockIdx.x;        // 0..7
    const int bh = blockIdx.y;
    const int bi = bh >> 4, hi = bh & 15;
    const int tid = threadIdx.x;
    const int warpId = tid >> 5, lane = tid & 31;
    const int wm = warpId & 3, wn = warpId >> 2;
    const int gr = lane >> 2, gc = lane & 3;

    const size_t OFF_NEW = (size_t)Bb * Ss * Dd;
    const float* newb = out + OFF_NEW + ((size_t)bh * Ss + qt * 128) * Ss;
    const uint32_t* Vtg = &g_Vt[(size_t)bh * Ss * 64];

    float acc[2][4][4];
#pragma unroll
    for (int m = 0; m < 2; m++)
#pragma unroll
        for (int t = 0; t < 4; t++)
#pragma unroll
            for (int e = 0; e < 4; e++) acc[m][t][e] = 0.0f;

    for (int kt = 0; kt < 16; kt++) {
        // P tile 128 x 64 (cvt fp32 -> tf32)
#pragma unroll
        for (int i = 0; i < 8; i++) {
            int idx = tid + i * 256;
            int r = idx >> 4, c4 = idx & 15;
            float4 v = *(const float4*)&newb[(size_t)r * 1024 + kt * 64 + c4 * 4];
            uint4 t = {f2tf(v.x), f2tf(v.y), f2tf(v.z), f2tf(v.w)};
            *(uint4*)&Ps[r * 68 + c4 * 4] = t;
        }
        // V tile 64 x 64 raw tf32 bits
#pragma unroll
        for (int i = 0; i < 4; i++) {
            int idx = tid + i * 256;
            int k = idx >> 4, c4 = idx & 15;
            uint4 v = *(const uint4*)&Vtg[((size_t)(kt * 64 + k)) * 64 + c4 * 4];
            *(uint4*)&Vs[k * 72 + c4 * 4] = v;
        }
        __syncthreads();

#pragma unroll
        for (int ks = 0; ks < 8; ks++) {
            const int kb = ks * 8;
            uint32_t af[2][4];
#pragma unroll
            for (int m = 0; m < 2; m++) {
                int m0 = wm * 32 + m * 16;
                af[m][0] = Ps[(m0 + gr) * 68 + kb + gc];
                af[m][1] = Ps[(m0 + gr + 8) * 68 + kb + gc];
                af[m][2] = Ps[(m0 + gr) * 68 + kb + gc + 4];
                af[m][3] = Ps[(m0 + gr + 8) * 68 + kb + gc + 4];
            }
#pragma unroll
            for (int t = 0; t < 4; t++) {
                int n0 = wn * 32 + t * 8;
                uint32_t bf[2];
                bf[0] = Vs[(kb + gc) * 72 + n0 + gr];
                bf[1] = Vs[(kb + gc + 4) * 72 + n0 + gr];
                mma_tf32(acc[0][t], af[0], bf);
                mma_tf32(acc[1][t], af[1], bf);
            }
        }
        __syncthreads();
    }

#pragma unroll
    for (int m = 0; m < 2; m++) {
        int row0 = qt * 128 + wm * 32 + m * 16 + gr;
#pragma unroll
        for (int t = 0; t < 4; t++) {
            int col = hi * 64 + wn * 32 + t * 8 + gc * 2;
            float2 v0 = {acc[m][t][0], acc[m][t][1]};
            float2 v1 = {acc[m][t][2], acc[m][t][3]};
            *(float2*)&out[((size_t)(bi * Ss + row0)) * Dd + col] = v0;
            *(float2*)&out[((size_t)(bi * Ss + row0 + 8)) * Dd + col] = v1;
        }
    }
}

// ---------------- launch ----------------------------------------------------------
extern "C" void kernel_launch(void* const* d_in, const int* in_sizes, int n_in,
                              void* d_out, int out_size)
{
    (void)in_sizes; (void)n_in; (void)out_size;
    const float* hidden = (const float*)d_in[0];
    const float* mask   = (const float*)d_in[1];
    const float* ctxemb = (const float*)d_in[2];
    const float* Wq = (const float*)d_in[3];  const float* bq = (const float*)d_in[4];
    const float* Wk = (const float*)d_in[5];  const float* bk = (const float*)d_in[6];
    const float* Wv = (const float*)d_in[7];  const float* bv = (const float*)d_in[8];
    const float* Wcq = (const float*)d_in[9]; const float* bcq = (const float*)d_in[10];
    const float* Wck = (const float*)d_in[11];const float* bck = (const float*)d_in[12];
    const float* wlqc = (const float*)d_in[13];
    const float* wlqq = (const float*)d_in[14];
    const float* wlkc = (const float*)d_in[15];
    const float* wlkk = (const float*)d_in[16];
    float* out = (float*)d_out;

    cudaFuncSetAttribute(proj_mma, cudaFuncAttributeMaxDynamicSharedMemorySize, PROJ_SMEM);
    cudaFuncSetAttribute(attn_ab, cudaFuncAttributeMaxDynamicSharedMemorySize, ATTN_SMEM);
    cudaFuncSetAttribute(pv_gemm, cudaFuncAttributeMaxDynamicSharedMemorySize, PV_SMEM);

    // user launch index 3 = attn_ab (gets profiled by ncu)
    cqck_conv<<<32, 256>>>(ctxemb, hidden, Wq, Wk, Wv, Wcq, bcq, Wck, bck);   // 0
    qsig_kernel<<<dim3(16, 16, Bb), 256>>>(mask);                             // 1
    proj_mma<<<dim3(8, 32, 3), 256, PROJ_SMEM>>>(bq, bk, bv);                 // 2
    attn_ab<<<dim3(32, 64), 512, ATTN_SMEM>>>(mask, out, wlqc, wlqq, wlkc, wlkk); // 3
    pv_gemm<<<dim3(8, 64), 256, PV_SMEM>>>(out);                              // 4
}